// round 14
// baseline (speedup 1.0000x reference)
#include <cstdint>
#include <cuda_runtime.h>
#include <cuda_bf16.h>
#include <mma.h>

using namespace nvcuda;

// Problem dims
#define B_   64
#define T_   1024
#define H_   512
#define M_   (B_ * T_)      // 65536 rows
#define L_   4
#define G3H  (3 * H_)       // 1536

// ---------------- static device scratch (no runtime allocation) ----------------
__device__ float        g_hA[(size_t)M_ * H_];            // input-proj h / final ys (fp32)
__device__ float        g_hB[(size_t)M_ * H_];            // MLP intermediate
__device__ float        g_gi[(size_t)M_ * G3H];           // layer-0 gi (402 MB)
__device__ unsigned int g_ys[(size_t)L_ * T_ * B_ * H_];  // packed (hi,lo) ys per layer
__device__ int          g_cnt[L_ * 2 * 32];               // per-(layer,half) counters, 128B apart

// ---------------- helpers ----------------
__device__ __forceinline__ void split_bf16(float v, __nv_bfloat16& hi, __nv_bfloat16& lo) {
    hi = __float2bfloat16(v);
    lo = __float2bfloat16(v - __bfloat162float(hi));
}
__device__ __forceinline__ float fast_sigmoid(float x) {
    return __fdividef(1.0f, 1.0f + __expf(-x));
}
__device__ __forceinline__ float fast_tanh(float x) {
    float e = __expf(-2.0f * x);
    return __fdividef(1.0f - e, 1.0f + e);
}
__device__ __forceinline__ float unpack_f(unsigned int p) {
    return __bfloat162float(__ushort_as_bfloat16((unsigned short)(p & 0xFFFF))) +
           __bfloat162float(__ushort_as_bfloat16((unsigned short)(p >> 16)));
}
__device__ __forceinline__ void spin_ge(int* cnt, int target) {
    int v;
    do { asm volatile("ld.acquire.gpu.global.s32 %0, [%1];" : "=r"(v) : "l"(cnt)); } while (v < target);
}

// =================================================================================
// hbinit: zero wavefront counters
// =================================================================================
__global__ __launch_bounds__(256)
void hbinit_kernel()
{
    if (blockIdx.x == 0 && threadIdx.x < L_ * 2 * 32)
        g_cnt[threadIdx.x] = 0;
}

// =================================================================================
// GEMM (identical to R6/R12): C[M,N] = act(A[M,K] @ W[N,K]^T + bias[N])
// =================================================================================
#define BM 128
#define BN 128
#define BK 32
#define GLD 40

template<int RELU>
__global__ __launch_bounds__(256)
void gemm_kernel(const float* __restrict__ A, const float* __restrict__ W,
                 const float* __restrict__ bias, float* __restrict__ C,
                 int M, int N, int K)
{
    __shared__ __nv_bfloat16 sAh[BM * GLD];
    __shared__ __nv_bfloat16 sAl[BM * GLD];
    __shared__ __nv_bfloat16 sBh[BN * GLD];
    __shared__ __nv_bfloat16 sBl[BN * GLD];

    const int tid  = threadIdx.x;
    const int m0   = blockIdx.y * BM;
    const int n0   = blockIdx.x * BN;
    const int w    = tid >> 5;
    const int lane = tid & 31;
    const int wm   = w >> 2;
    const int wn   = w & 3;

    wmma::fragment<wmma::accumulator, 16, 16, 16, float> acc[4][2];
    #pragma unroll
    for (int i = 0; i < 4; i++)
        #pragma unroll
        for (int j = 0; j < 2; j++)
            wmma::fill_fragment(acc[i][j], 0.0f);

    const int r0 = tid >> 3;
    const int c4 = (tid & 7) * 4;

    for (int k0 = 0; k0 < K; k0 += BK) {
        #pragma unroll
        for (int rr = 0; rr < 4; rr++) {
            int r = r0 + rr * 32;
            float4 va = *(const float4*)&A[(size_t)(m0 + r) * K + k0 + c4];
            float4 vb = *(const float4*)&W[(size_t)(n0 + r) * K + k0 + c4];
            __nv_bfloat16 h, l;
            int base = r * GLD + c4;
            split_bf16(va.x, h, l); sAh[base + 0] = h; sAl[base + 0] = l;
            split_bf16(va.y, h, l); sAh[base + 1] = h; sAl[base + 1] = l;
            split_bf16(va.z, h, l); sAh[base + 2] = h; sAl[base + 2] = l;
            split_bf16(va.w, h, l); sAh[base + 3] = h; sAl[base + 3] = l;
            split_bf16(vb.x, h, l); sBh[base + 0] = h; sBl[base + 0] = l;
            split_bf16(vb.y, h, l); sBh[base + 1] = h; sBl[base + 1] = l;
            split_bf16(vb.z, h, l); sBh[base + 2] = h; sBl[base + 2] = l;
            split_bf16(vb.w, h, l); sBh[base + 3] = h; sBl[base + 3] = l;
        }
        __syncthreads();

        #pragma unroll
        for (int kk = 0; kk < BK; kk += 16) {
            wmma::fragment<wmma::matrix_b, 16, 16, 16, __nv_bfloat16, wmma::col_major> bh[2], bl[2];
            #pragma unroll
            for (int nf = 0; nf < 2; nf++) {
                wmma::load_matrix_sync(bh[nf], &sBh[(wn * 32 + nf * 16) * GLD + kk], GLD);
                wmma::load_matrix_sync(bl[nf], &sBl[(wn * 32 + nf * 16) * GLD + kk], GLD);
            }
            #pragma unroll
            for (int mf = 0; mf < 4; mf++) {
                wmma::fragment<wmma::matrix_a, 16, 16, 16, __nv_bfloat16, wmma::row_major> ah, al;
                wmma::load_matrix_sync(ah, &sAh[(wm * 64 + mf * 16) * GLD + kk], GLD);
                wmma::load_matrix_sync(al, &sAl[(wm * 64 + mf * 16) * GLD + kk], GLD);
                #pragma unroll
                for (int nf = 0; nf < 2; nf++) {
                    wmma::mma_sync(acc[mf][nf], ah, bh[nf], acc[mf][nf]);
                    wmma::mma_sync(acc[mf][nf], ah, bl[nf], acc[mf][nf]);
                    wmma::mma_sync(acc[mf][nf], al, bh[nf], acc[mf][nf]);
                }
            }
        }
        __syncthreads();
    }

    float* scr   = (float*)sAh;
    float* myscr = scr + w * 320;
    #pragma unroll
    for (int mf = 0; mf < 4; mf++) {
        #pragma unroll
        for (int nf = 0; nf < 2; nf++) {
            wmma::store_matrix_sync(myscr, acc[mf][nf], 20, wmma::mem_row_major);
            __syncwarp();
            #pragma unroll
            for (int e = 0; e < 8; e++) {
                int idx = e * 32 + lane;
                int r = idx >> 4, c = idx & 15;
                int row = m0 + wm * 64 + mf * 16 + r;
                int col = n0 + wn * 32 + nf * 16 + c;
                float v = myscr[r * 20 + c] + __ldg(&bias[col]);
                if (RELU) v = fmaxf(v, 0.0f);
                C[(size_t)row * N + col] = v;
            }
            __syncwarp();
        }
    }
}

// =================================================================================
// WAVEFRONT GRU scan v2 (R14):
//  - half-granular counters: release/wait per 32-row batch half (finer wave)
//  - layer-0 gi0 register prefetch (pacesetter epilogue off global latency)
//  - stage-B register prefetch: input-tile LDGs issued before gh MMA phase
// =================================================================================
#define SW      520
#define NBLK    32
#define NTHR    384
// smem offsets (bytes)
#define OFF_HH    0                         // 32 x SW bf16  (33280)
#define OFF_HL    33280
#define OFF_WIHH  66560                     // 48 x SW bf16  (49920)
#define OFF_WIHL  116480
#define OFF_P     166400                    // [4][32][64] fp32 (32768)
#define OFF_SBH   199168                    // 48 fp32
#define OFF_SBI   199360                    // 48 fp32
#define OFF_HOF   199552                    // 32x16 fp32 (2048)
#define SCAN_SMEM 201600

typedef wmma::fragment<wmma::matrix_b, 16, 16, 16, __nv_bfloat16, wmma::col_major> bfrag_t;
typedef wmma::fragment<wmma::matrix_a, 16, 16, 16, __nv_bfloat16, wmma::row_major> afrag_t;
typedef wmma::fragment<wmma::accumulator, 16, 16, 16, float> cfrag_t;

__global__ __launch_bounds__(NTHR)
void scan_wave(const float* __restrict__ gi0, const float* __restrict__ w_ih,
               const float* __restrict__ w_hh, const float* __restrict__ b_ih,
               const float* __restrict__ b_hh, float* __restrict__ ysout)
{
    extern __shared__ char smem[];
    __nv_bfloat16* hh   = (__nv_bfloat16*)(smem + OFF_HH);
    __nv_bfloat16* hl   = (__nv_bfloat16*)(smem + OFF_HL);
    __nv_bfloat16* wihh = (__nv_bfloat16*)(smem + OFF_WIHH);
    __nv_bfloat16* wihl = (__nv_bfloat16*)(smem + OFF_WIHL);
    float* P   = (float*)(smem + OFF_P);
    float* sbh = (float*)(smem + OFF_SBH);
    float* sbi = (float*)(smem + OFF_SBI);
    float* hof = (float*)(smem + OFF_HOF);

    const int tid   = threadIdx.x;
    const int layer = blockIdx.x >> 5;
    const int blk   = blockIdx.x & 31;
    const int c0    = blk * 16;
    const int w     = tid >> 5;
    const int ntile = w % 3;       // gate r/z/n
    const int kq    = w / 3;       // K quarter (128)

    const float* whh_l = w_hh + (size_t)layer * G3H * H_;
    const float* wih_l = w_ih + (size_t)layer * G3H * H_;

    // ---- init: whh slice -> register fragments (use wihh region as temp) ----
    bfrag_t bhf[8], blf[8];
    {
        __nv_bfloat16* wtmp = wihh;
        for (int i = tid; i < 48 * H_; i += NTHR) {
            int rl = i >> 9, k = i & 511;
            int grow = (rl >> 4) * H_ + c0 + (rl & 15);
            wtmp[rl * SW + k] = __float2bfloat16(whh_l[(size_t)grow * H_ + k]);
        }
        __syncthreads();
        #pragma unroll
        for (int i = 0; i < 8; i++)
            wmma::load_matrix_sync(bhf[i], wtmp + ntile * 16 * SW + kq * 128 + i * 16, SW);
        __syncthreads();
        for (int i = tid; i < 48 * H_; i += NTHR) {
            int rl = i >> 9, k = i & 511;
            int grow = (rl >> 4) * H_ + c0 + (rl & 15);
            float v = whh_l[(size_t)grow * H_ + k];
            wtmp[rl * SW + k] = __float2bfloat16(v - __bfloat162float(__float2bfloat16(v)));
        }
        __syncthreads();
        #pragma unroll
        for (int i = 0; i < 8; i++)
            wmma::load_matrix_sync(blf[i], wtmp + ntile * 16 * SW + kq * 128 + i * 16, SW);
        __syncthreads();
    }
    // ---- wih slice pair into smem (layers >= 1) ----
    if (layer > 0) {
        for (int i = tid; i < 48 * H_; i += NTHR) {
            int rl = i >> 9, k = i & 511;
            int grow = (rl >> 4) * H_ + c0 + (rl & 15);
            float v = wih_l[(size_t)grow * H_ + k];
            __nv_bfloat16 hi, lo; split_bf16(v, hi, lo);
            wihh[rl * SW + k] = hi;
            wihl[rl * SW + k] = lo;
        }
    }
    if (tid < 48) {
        int grow = (tid >> 4) * H_ + c0 + (tid & 15);
        sbh[tid] = b_hh[(size_t)layer * G3H + grow];
        sbi[tid] = b_ih[(size_t)layer * G3H + grow];
    }
    __syncthreads();

    // epilogue element ownership (up to 2 per thread per half)
    const int e0 = tid;            // < 512 always? tid<384 -> yes
    const int e1 = tid + NTHR;     // < 512 only for tid < 128

    for (int t = 0; t < T_; t++) {
        for (int half = 0; half < 2; half++) {
            const int rowbase = half * 32;
            int* own  = &g_cnt[(layer * 2 + half) * 32];
            int* prev = &g_cnt[((layer - (layer > 0)) * 2 + half) * 32];

            // ---- wait: own ys(t-1) half done; input ys(layer-1, t) half done ----
            if (tid == 0) {
                spin_ge(own, NBLK * t);
                if (layer > 0) spin_ge(prev, NBLK * (t + 1));
            }
            __syncthreads();

            // ---- layer-0: prefetch gi0 for this half's epilogue elements ----
            float g0r0 = 0.f, g0z0 = 0.f, g0n0 = 0.f, g0r1 = 0.f, g0z1 = 0.f, g0n1 = 0.f;
            if (layer == 0) {
                {
                    int b = rowbase + (e0 >> 4), c = c0 + (e0 & 15);
                    const float* gp = gi0 + ((size_t)b * T_ + t) * G3H + c;
                    g0r0 = __ldg(gp); g0z0 = __ldg(gp + H_); g0n0 = __ldg(gp + 2 * H_);
                }
                if (e1 < 512) {
                    int b = rowbase + (e1 >> 4), c = c0 + (e1 & 15);
                    const float* gp = gi0 + ((size_t)b * T_ + t) * G3H + c;
                    g0r1 = __ldg(gp); g0z1 = __ldg(gp + H_); g0n1 = __ldg(gp + 2 * H_);
                }
            }

            // ---- stage-B register prefetch (layers >= 1): 6 chunks/thread ----
            uint4 pf[6];
            const unsigned int* srcB = g_ys + (((size_t)(layer - (layer > 0)) * T_ + t) * B_ + rowbase) * H_;
            if (layer > 0) {
                #pragma unroll
                for (int k = 0; k < 6; k++) {
                    int i = tid + k * NTHR;
                    int row = i >> 7, cc = (i & 127) * 4;
                    pf[k] = __ldcg((const uint4*)(srcB + (size_t)row * H_ + cc));
                }
            }

            // ---- stage A: own ys[layer][t-1] half (zeros at t==0) ----
            if (t == 0) {
                for (int i = tid; i < 32 * SW / 4; i += NTHR)
                    ((uint2*)hh)[i] = make_uint2(0u, 0u);
                for (int i = tid; i < 32 * SW / 4; i += NTHR)
                    ((uint2*)hl)[i] = make_uint2(0u, 0u);
                for (int i = tid; i < 512; i += NTHR)
                    hof[i] = 0.0f;
            } else {
                const unsigned int* src = g_ys + (((size_t)layer * T_ + (t - 1)) * B_ + rowbase) * H_;
                for (int i = tid; i < 4096; i += NTHR) {
                    int row = i >> 7;
                    int cc  = (i & 127) * 4;
                    uint4 v = __ldcg((const uint4*)(src + (size_t)row * H_ + cc));
                    unsigned int h01 = __byte_perm(v.x, v.y, 0x5410);
                    unsigned int l01 = __byte_perm(v.x, v.y, 0x7632);
                    unsigned int h23 = __byte_perm(v.z, v.w, 0x5410);
                    unsigned int l23 = __byte_perm(v.z, v.w, 0x7632);
                    *(uint2*)&hh[row * SW + cc] = make_uint2(h01, h23);
                    *(uint2*)&hl[row * SW + cc] = make_uint2(l01, l23);
                    if ((unsigned)(cc - c0) < 16u) {
                        int jb = cc - c0;
                        hof[row * 16 + jb + 0] = unpack_f(v.x);
                        hof[row * 16 + jb + 1] = unpack_f(v.y);
                        hof[row * 16 + jb + 2] = unpack_f(v.z);
                        hof[row * 16 + jb + 3] = unpack_f(v.w);
                    }
                }
            }
            __syncthreads();

            // ---- gh MMA (register-resident whh) ----
            cfrag_t accs[2];
            wmma::fill_fragment(accs[0], 0.0f);
            wmma::fill_fragment(accs[1], 0.0f);
            const int kb = kq * 128;
            #pragma unroll
            for (int m = 0; m < 2; m++) {
                #pragma unroll
                for (int i = 0; i < 8; i++) {
                    afrag_t ah, al;
                    wmma::load_matrix_sync(ah, hh + (m * 16) * SW + kb + i * 16, SW);
                    wmma::load_matrix_sync(al, hl + (m * 16) * SW + kb + i * 16, SW);
                    wmma::mma_sync(accs[m], ah, bhf[i], accs[m]);
                    wmma::mma_sync(accs[m], ah, blf[i], accs[m]);
                    wmma::mma_sync(accs[m], al, bhf[i], accs[m]);
                }
            }
            if (ntile == 2) {   // n gate: store h_n now, reset for i_n
                #pragma unroll
                for (int m = 0; m < 2; m++) {
                    wmma::store_matrix_sync(P + kq * 2048 + m * 16 * 64 + 32, accs[m], 64, wmma::mem_row_major);
                    wmma::fill_fragment(accs[m], 0.0f);
                }
            }
            __syncthreads();   // gh reads done before stage-B overwrites buffer

            if (layer > 0) {
                // ---- stage B: write prefetched chunks + load remaining ----
                #pragma unroll
                for (int k = 0; k < 6; k++) {
                    int i = tid + k * NTHR;
                    int row = i >> 7, cc = (i & 127) * 4;
                    uint4 v = pf[k];
                    unsigned int h01 = __byte_perm(v.x, v.y, 0x5410);
                    unsigned int l01 = __byte_perm(v.x, v.y, 0x7632);
                    unsigned int h23 = __byte_perm(v.z, v.w, 0x5410);
                    unsigned int l23 = __byte_perm(v.z, v.w, 0x7632);
                    *(uint2*)&hh[row * SW + cc] = make_uint2(h01, h23);
                    *(uint2*)&hl[row * SW + cc] = make_uint2(l01, l23);
                }
                for (int i = tid + 6 * NTHR; i < 4096; i += NTHR) {
                    int row = i >> 7, cc = (i & 127) * 4;
                    uint4 v = __ldcg((const uint4*)(srcB + (size_t)row * H_ + cc));
                    unsigned int h01 = __byte_perm(v.x, v.y, 0x5410);
                    unsigned int l01 = __byte_perm(v.x, v.y, 0x7632);
                    unsigned int h23 = __byte_perm(v.z, v.w, 0x5410);
                    unsigned int l23 = __byte_perm(v.z, v.w, 0x7632);
                    *(uint2*)&hh[row * SW + cc] = make_uint2(h01, h23);
                    *(uint2*)&hl[row * SW + cc] = make_uint2(l01, l23);
                }
                __syncthreads();

                // ---- gi MMA (smem-pair wih); r,z accumulate into fused accs ----
                #pragma unroll
                for (int m = 0; m < 2; m++) {
                    #pragma unroll
                    for (int i = 0; i < 8; i++) {
                        afrag_t ah, al;
                        bfrag_t bwh, bwl;
                        wmma::load_matrix_sync(ah, hh + (m * 16) * SW + kb + i * 16, SW);
                        wmma::load_matrix_sync(al, hl + (m * 16) * SW + kb + i * 16, SW);
                        wmma::load_matrix_sync(bwh, wihh + ntile * 16 * SW + kb + i * 16, SW);
                        wmma::load_matrix_sync(bwl, wihl + ntile * 16 * SW + kb + i * 16, SW);
                        wmma::mma_sync(accs[m], ah, bwh, accs[m]);
                        wmma::mma_sync(accs[m], ah, bwl, accs[m]);
                        wmma::mma_sync(accs[m], al, bwh, accs[m]);
                    }
                }
            }

            // ---- store partials: r,z fused at cols 0/16; i_n at col 48 ----
            {
                int colb = (ntile < 2) ? ntile * 16 : 48;
                if (ntile < 2 || layer > 0) {
                    #pragma unroll
                    for (int m = 0; m < 2; m++)
                        wmma::store_matrix_sync(P + kq * 2048 + m * 16 * 64 + colb, accs[m], 64, wmma::mem_row_major);
                }
            }
            __syncthreads();

            // ---- epilogue: 512 elements (32 rows x 16 cols), <=2 per thread ----
            #pragma unroll
            for (int e = 0; e < 2; e++) {
                int idx = (e == 0) ? e0 : e1;
                if (idx >= 512) break;
                int rr = idx >> 4, j = idx & 15;
                int b = rowbase + rr;
                float pr = 0.f, pz = 0.f, pn = 0.f, pi = 0.f;
                #pragma unroll
                for (int q = 0; q < 4; q++) {
                    int base = q * 2048 + rr * 64;
                    pr += P[base + j];
                    pz += P[base + 16 + j];
                    pn += P[base + 32 + j];
                    pi += P[base + 48 + j];
                }
                float r, z, n;
                if (layer == 0) {
                    float ir = (e == 0) ? g0r0 : g0r1;
                    float iz = (e == 0) ? g0z0 : g0z1;
                    float in = (e == 0) ? g0n0 : g0n1;
                    r = fast_sigmoid(ir + pr + sbh[j]);
                    z = fast_sigmoid(iz + pz + sbh[16 + j]);
                    n = fast_tanh(in + r * (pn + sbh[32 + j]));
                } else {
                    r = fast_sigmoid(pr + sbh[j] + sbi[j]);
                    z = fast_sigmoid(pz + sbh[16 + j] + sbi[16 + j]);
                    n = fast_tanh(pi + sbi[32 + j] + r * (pn + sbh[32 + j]));
                }
                float ho = hof[rr * 16 + j];
                float hn = (1.0f - z) * n + z * ho;
                __nv_bfloat16 hi, lo; split_bf16(hn, hi, lo);
                unsigned int packed = ((unsigned int)__bfloat16_as_ushort(hi)) |
                                      ((unsigned int)__bfloat16_as_ushort(lo) << 16);
                __stcg(&g_ys[(((size_t)layer * T_ + t) * B_ + b) * H_ + c0 + j], packed);
                if (layer == 3)
                    ysout[((size_t)b * T_ + t) * H_ + c0 + j] = hn;
            }
            __syncthreads();   // all ys stores done before release

            // ---- arrive: release this half's ys writes ----
            if (tid == 0)
                asm volatile("red.release.gpu.global.add.s32 [%0], 1;" :: "l"(own) : "memory");
        }   // halves
    }
}

// =================================================================================
// Orchestration — kernel sequence: gemm1(1), gemm0(2), hbinit(3), scan(4 <- ncu)
// =================================================================================
extern "C" void kernel_launch(void* const* d_in, const int* in_sizes, int n_in,
                              void* d_out, int out_size)
{
    const float* x    = (const float*)d_in[0];
    const float* w_in = (const float*)d_in[1];
    const float* b_in = (const float*)d_in[2];
    const float* w_ih = (const float*)d_in[3];
    const float* w_hh = (const float*)d_in[4];
    const float* b_ih = (const float*)d_in[5];
    const float* b_hh = (const float*)d_in[6];
    const float* w_o1 = (const float*)d_in[7];
    const float* b_o1 = (const float*)d_in[8];
    const float* w_o2 = (const float*)d_in[9];
    const float* b_o2 = (const float*)d_in[10];
    float* out = (float*)d_out;
    (void)in_sizes; (void)n_in; (void)out_size;

    float *hA, *hB, *gi;
    cudaGetSymbolAddress((void**)&hA, g_hA);
    cudaGetSymbolAddress((void**)&hB, g_hB);
    cudaGetSymbolAddress((void**)&gi, g_gi);

    cudaFuncSetAttribute(scan_wave, cudaFuncAttributeMaxDynamicSharedMemorySize, SCAN_SMEM);

    dim3 blk(256);

    // 1: input Linear + ReLU -> hA
    gemm_kernel<1><<<dim3(H_ / BN, M_ / BM), blk>>>(x, w_in, b_in, hA, M_, H_, H_);
    // 2: layer-0 gi (bias b_ih[0] folded)
    gemm_kernel<0><<<dim3(G3H / BN, M_ / BM), blk>>>(
        hA, w_ih, b_ih, gi, M_, G3H, H_);
    // 3: zero wavefront counters
    hbinit_kernel<<<1, 256>>>();
    // 4: the whole 4-layer wavefront recurrence (ncu captured slot)
    scan_wave<<<NBLK * L_, NTHR, SCAN_SMEM>>>(gi, w_ih, w_hh, b_ih, b_hh, hA);
    // 5/6: output MLP
    gemm_kernel<1><<<dim3(H_ / BN, M_ / BM), blk>>>(hA, w_o1, b_o1, hB, M_, H_, H_);
    gemm_kernel<0><<<dim3(H_ / BN, M_ / BM), blk>>>(hB, w_o2, b_o2, out, M_, H_, H_);
}

// round 15
// speedup vs baseline: 1.1662x; 1.1662x over previous
#include <cstdint>
#include <cuda_runtime.h>
#include <cuda_bf16.h>
#include <mma.h>

using namespace nvcuda;

// Problem dims
#define B_   64
#define T_   1024
#define H_   512
#define M_   (B_ * T_)      // 65536 rows
#define L_   4
#define G3H  (3 * H_)       // 1536

// ---------------- static device scratch (no runtime allocation) ----------------
__device__ float        g_hA[(size_t)M_ * H_];            // input-proj h / final ys (fp32)
__device__ float        g_hB[(size_t)M_ * H_];            // MLP intermediate
__device__ float        g_gi[(size_t)M_ * G3H];           // layer-0 gi (402 MB)
__device__ unsigned int g_ys[(size_t)L_ * T_ * B_ * H_];  // packed (hi,lo) ys per layer
__device__ int          g_cnt[L_ * 32];                   // per-layer counters, 128B apart

// ---------------- helpers ----------------
__device__ __forceinline__ void split_bf16(float v, __nv_bfloat16& hi, __nv_bfloat16& lo) {
    hi = __float2bfloat16(v);
    lo = __float2bfloat16(v - __bfloat162float(hi));
}
__device__ __forceinline__ float fast_sigmoid(float x) {
    return __fdividef(1.0f, 1.0f + __expf(-x));
}
__device__ __forceinline__ float fast_tanh(float x) {
    float e = __expf(-2.0f * x);
    return __fdividef(1.0f - e, 1.0f + e);
}
__device__ __forceinline__ float unpack_f(unsigned int p) {
    return __bfloat162float(__ushort_as_bfloat16((unsigned short)(p & 0xFFFF))) +
           __bfloat162float(__ushort_as_bfloat16((unsigned short)(p >> 16)));
}
__device__ __forceinline__ void spin_ge(int* cnt, int target) {
    int v;
    do { asm volatile("ld.acquire.gpu.global.s32 %0, [%1];" : "=r"(v) : "l"(cnt)); } while (v < target);
}

// =================================================================================
// hbinit: zero wavefront counters
// =================================================================================
__global__ __launch_bounds__(256)
void hbinit_kernel()
{
    if (blockIdx.x == 0 && threadIdx.x < L_ * 32)
        g_cnt[threadIdx.x] = 0;
}

// =================================================================================
// GEMM (identical to R6/R12): C[M,N] = act(A[M,K] @ W[N,K]^T + bias[N])
// =================================================================================
#define BM 128
#define BN 128
#define BK 32
#define GLD 40

template<int RELU>
__global__ __launch_bounds__(256)
void gemm_kernel(const float* __restrict__ A, const float* __restrict__ W,
                 const float* __restrict__ bias, float* __restrict__ C,
                 int M, int N, int K)
{
    __shared__ __nv_bfloat16 sAh[BM * GLD];
    __shared__ __nv_bfloat16 sAl[BM * GLD];
    __shared__ __nv_bfloat16 sBh[BN * GLD];
    __shared__ __nv_bfloat16 sBl[BN * GLD];

    const int tid  = threadIdx.x;
    const int m0   = blockIdx.y * BM;
    const int n0   = blockIdx.x * BN;
    const int w    = tid >> 5;
    const int lane = tid & 31;
    const int wm   = w >> 2;
    const int wn   = w & 3;

    wmma::fragment<wmma::accumulator, 16, 16, 16, float> acc[4][2];
    #pragma unroll
    for (int i = 0; i < 4; i++)
        #pragma unroll
        for (int j = 0; j < 2; j++)
            wmma::fill_fragment(acc[i][j], 0.0f);

    const int r0 = tid >> 3;
    const int c4 = (tid & 7) * 4;

    for (int k0 = 0; k0 < K; k0 += BK) {
        #pragma unroll
        for (int rr = 0; rr < 4; rr++) {
            int r = r0 + rr * 32;
            float4 va = *(const float4*)&A[(size_t)(m0 + r) * K + k0 + c4];
            float4 vb = *(const float4*)&W[(size_t)(n0 + r) * K + k0 + c4];
            __nv_bfloat16 h, l;
            int base = r * GLD + c4;
            split_bf16(va.x, h, l); sAh[base + 0] = h; sAl[base + 0] = l;
            split_bf16(va.y, h, l); sAh[base + 1] = h; sAl[base + 1] = l;
            split_bf16(va.z, h, l); sAh[base + 2] = h; sAl[base + 2] = l;
            split_bf16(va.w, h, l); sAh[base + 3] = h; sAl[base + 3] = l;
            split_bf16(vb.x, h, l); sBh[base + 0] = h; sBl[base + 0] = l;
            split_bf16(vb.y, h, l); sBh[base + 1] = h; sBl[base + 1] = l;
            split_bf16(vb.z, h, l); sBh[base + 2] = h; sBl[base + 2] = l;
            split_bf16(vb.w, h, l); sBh[base + 3] = h; sBl[base + 3] = l;
        }
        __syncthreads();

        #pragma unroll
        for (int kk = 0; kk < BK; kk += 16) {
            wmma::fragment<wmma::matrix_b, 16, 16, 16, __nv_bfloat16, wmma::col_major> bh[2], bl[2];
            #pragma unroll
            for (int nf = 0; nf < 2; nf++) {
                wmma::load_matrix_sync(bh[nf], &sBh[(wn * 32 + nf * 16) * GLD + kk], GLD);
                wmma::load_matrix_sync(bl[nf], &sBl[(wn * 32 + nf * 16) * GLD + kk], GLD);
            }
            #pragma unroll
            for (int mf = 0; mf < 4; mf++) {
                wmma::fragment<wmma::matrix_a, 16, 16, 16, __nv_bfloat16, wmma::row_major> ah, al;
                wmma::load_matrix_sync(ah, &sAh[(wm * 64 + mf * 16) * GLD + kk], GLD);
                wmma::load_matrix_sync(al, &sAl[(wm * 64 + mf * 16) * GLD + kk], GLD);
                #pragma unroll
                for (int nf = 0; nf < 2; nf++) {
                    wmma::mma_sync(acc[mf][nf], ah, bh[nf], acc[mf][nf]);
                    wmma::mma_sync(acc[mf][nf], ah, bl[nf], acc[mf][nf]);
                    wmma::mma_sync(acc[mf][nf], al, bh[nf], acc[mf][nf]);
                }
            }
        }
        __syncthreads();
    }

    float* scr   = (float*)sAh;
    float* myscr = scr + w * 320;
    #pragma unroll
    for (int mf = 0; mf < 4; mf++) {
        #pragma unroll
        for (int nf = 0; nf < 2; nf++) {
            wmma::store_matrix_sync(myscr, acc[mf][nf], 20, wmma::mem_row_major);
            __syncwarp();
            #pragma unroll
            for (int e = 0; e < 8; e++) {
                int idx = e * 32 + lane;
                int r = idx >> 4, c = idx & 15;
                int row = m0 + wm * 64 + mf * 16 + r;
                int col = n0 + wn * 32 + nf * 16 + c;
                float v = myscr[r * 20 + c] + __ldg(&bias[col]);
                if (RELU) v = fmaxf(v, 0.0f);
                C[(size_t)row * N + col] = v;
            }
            __syncwarp();
        }
    }
}

// =================================================================================
// WAVEFRONT GRU scan v3 (R15 = R13 + broken accumulator chains):
//  - m-interleaved MMA loops: 2 independent chains instead of 2 sequential
//  - 2-way pass split per m: accA <- ah*bh + ah*bl (depth 16), accB <- al*bh (8)
//    -> 4 independent dependency chains per warp, summed at store
//  - everything else identical to R13 (tick counters, no prefetch arrays)
// =================================================================================
#define SW      520
#define NBLK    32
#define NTHR    384
// smem offsets (bytes)
#define OFF_HH    0                         // 32 x SW bf16  (33280)
#define OFF_HL    33280
#define OFF_WIHH  66560                     // 48 x SW bf16  (49920)
#define OFF_WIHL  116480
#define OFF_P     166400                    // [4][32][64] fp32 (32768)
#define OFF_SBH   199168                    // 48 fp32
#define OFF_SBI   199360                    // 48 fp32
#define OFF_HOF   199552                    // 32x16 fp32 (2048)
#define SCAN_SMEM 201600

typedef wmma::fragment<wmma::matrix_b, 16, 16, 16, __nv_bfloat16, wmma::col_major> bfrag_t;
typedef wmma::fragment<wmma::matrix_a, 16, 16, 16, __nv_bfloat16, wmma::row_major> afrag_t;
typedef wmma::fragment<wmma::accumulator, 16, 16, 16, float> cfrag_t;

__global__ __launch_bounds__(NTHR)
void scan_wave(const float* __restrict__ gi0, const float* __restrict__ w_ih,
               const float* __restrict__ w_hh, const float* __restrict__ b_ih,
               const float* __restrict__ b_hh, float* __restrict__ ysout)
{
    extern __shared__ char smem[];
    __nv_bfloat16* hh   = (__nv_bfloat16*)(smem + OFF_HH);
    __nv_bfloat16* hl   = (__nv_bfloat16*)(smem + OFF_HL);
    __nv_bfloat16* wihh = (__nv_bfloat16*)(smem + OFF_WIHH);
    __nv_bfloat16* wihl = (__nv_bfloat16*)(smem + OFF_WIHL);
    float* P   = (float*)(smem + OFF_P);
    float* sbh = (float*)(smem + OFF_SBH);
    float* sbi = (float*)(smem + OFF_SBI);
    float* hof = (float*)(smem + OFF_HOF);

    const int tid   = threadIdx.x;
    const int layer = blockIdx.x >> 5;
    const int blk   = blockIdx.x & 31;
    const int c0    = blk * 16;
    const int w     = tid >> 5;
    const int ntile = w % 3;       // gate r/z/n
    const int kq    = w / 3;       // K quarter (128)
    int* mycnt   = &g_cnt[layer * 32];
    int* prevcnt = &g_cnt[(layer > 0 ? layer - 1 : 0) * 32];

    const float* whh_l = w_hh + (size_t)layer * G3H * H_;
    const float* wih_l = w_ih + (size_t)layer * G3H * H_;

    // ---- init: whh slice -> register fragments (use wihh region as temp) ----
    bfrag_t bhf[8], blf[8];
    {
        __nv_bfloat16* wtmp = wihh;
        for (int i = tid; i < 48 * H_; i += NTHR) {
            int rl = i >> 9, k = i & 511;
            int grow = (rl >> 4) * H_ + c0 + (rl & 15);
            wtmp[rl * SW + k] = __float2bfloat16(whh_l[(size_t)grow * H_ + k]);
        }
        __syncthreads();
        #pragma unroll
        for (int i = 0; i < 8; i++)
            wmma::load_matrix_sync(bhf[i], wtmp + ntile * 16 * SW + kq * 128 + i * 16, SW);
        __syncthreads();
        for (int i = tid; i < 48 * H_; i += NTHR) {
            int rl = i >> 9, k = i & 511;
            int grow = (rl >> 4) * H_ + c0 + (rl & 15);
            float v = whh_l[(size_t)grow * H_ + k];
            wtmp[rl * SW + k] = __float2bfloat16(v - __bfloat162float(__float2bfloat16(v)));
        }
        __syncthreads();
        #pragma unroll
        for (int i = 0; i < 8; i++)
            wmma::load_matrix_sync(blf[i], wtmp + ntile * 16 * SW + kq * 128 + i * 16, SW);
        __syncthreads();
    }
    // ---- wih slice pair into smem (layers >= 1) ----
    if (layer > 0) {
        for (int i = tid; i < 48 * H_; i += NTHR) {
            int rl = i >> 9, k = i & 511;
            int grow = (rl >> 4) * H_ + c0 + (rl & 15);
            float v = wih_l[(size_t)grow * H_ + k];
            __nv_bfloat16 hi, lo; split_bf16(v, hi, lo);
            wihh[rl * SW + k] = hi;
            wihl[rl * SW + k] = lo;
        }
    }
    if (tid < 48) {
        int grow = (tid >> 4) * H_ + c0 + (tid & 15);
        sbh[tid] = b_hh[(size_t)layer * G3H + grow];
        sbi[tid] = b_ih[(size_t)layer * G3H + grow];
    }
    __syncthreads();

    for (int t = 0; t < T_; t++) {
        // ---- wait: own h(t-1) complete; input ys(layer-1, t) complete ----
        if (tid == 0) {
            spin_ge(mycnt, NBLK * t);
            if (layer > 0) spin_ge(prevcnt, NBLK * (t + 1));
        }
        __syncthreads();

        for (int half = 0; half < 2; half++) {
            const int rowbase = half * 32;

            // ---- stage A: own ys[layer][t-1] rows (zeros at t==0) ----
            if (t == 0) {
                for (int i = tid; i < 32 * SW / 4; i += NTHR)
                    ((uint2*)hh)[i] = make_uint2(0u, 0u);
                for (int i = tid; i < 32 * SW / 4; i += NTHR)
                    ((uint2*)hl)[i] = make_uint2(0u, 0u);
                for (int i = tid; i < 512; i += NTHR)
                    hof[i] = 0.0f;
            } else {
                const unsigned int* src = g_ys + (((size_t)layer * T_ + (t - 1)) * B_ + rowbase) * H_;
                for (int i = tid; i < 4096; i += NTHR) {
                    int row = i >> 7;
                    int cc  = (i & 127) * 4;
                    uint4 v = __ldcg((const uint4*)(src + (size_t)row * H_ + cc));
                    unsigned int h01 = __byte_perm(v.x, v.y, 0x5410);
                    unsigned int l01 = __byte_perm(v.x, v.y, 0x7632);
                    unsigned int h23 = __byte_perm(v.z, v.w, 0x5410);
                    unsigned int l23 = __byte_perm(v.z, v.w, 0x7632);
                    *(uint2*)&hh[row * SW + cc] = make_uint2(h01, h23);
                    *(uint2*)&hl[row * SW + cc] = make_uint2(l01, l23);
                    if ((unsigned)(cc - c0) < 16u) {
                        int jb = cc - c0;
                        hof[row * 16 + jb + 0] = unpack_f(v.x);
                        hof[row * 16 + jb + 1] = unpack_f(v.y);
                        hof[row * 16 + jb + 2] = unpack_f(v.z);
                        hof[row * 16 + jb + 3] = unpack_f(v.w);
                    }
                }
            }
            __syncthreads();

            // ---- gh MMA: m-interleaved, 4 independent accumulator chains ----
            cfrag_t accA[2], accB[2];
            wmma::fill_fragment(accA[0], 0.0f); wmma::fill_fragment(accA[1], 0.0f);
            wmma::fill_fragment(accB[0], 0.0f); wmma::fill_fragment(accB[1], 0.0f);
            const int kb = kq * 128;
            #pragma unroll
            for (int i = 0; i < 8; i++) {
                afrag_t ah0, al0, ah1, al1;
                wmma::load_matrix_sync(ah0, hh + kb + i * 16, SW);
                wmma::load_matrix_sync(ah1, hh + 16 * SW + kb + i * 16, SW);
                wmma::load_matrix_sync(al0, hl + kb + i * 16, SW);
                wmma::load_matrix_sync(al1, hl + 16 * SW + kb + i * 16, SW);
                wmma::mma_sync(accA[0], ah0, bhf[i], accA[0]);
                wmma::mma_sync(accA[1], ah1, bhf[i], accA[1]);
                wmma::mma_sync(accB[0], al0, bhf[i], accB[0]);
                wmma::mma_sync(accB[1], al1, bhf[i], accB[1]);
                wmma::mma_sync(accA[0], ah0, blf[i], accA[0]);
                wmma::mma_sync(accA[1], ah1, blf[i], accA[1]);
            }
            if (ntile == 2) {   // n gate: store h_n sum now, reset for i_n
                #pragma unroll
                for (int m = 0; m < 2; m++) {
                    #pragma unroll
                    for (int e = 0; e < accA[m].num_elements; e++)
                        accA[m].x[e] += accB[m].x[e];
                    wmma::store_matrix_sync(P + kq * 2048 + m * 16 * 64 + 32, accA[m], 64, wmma::mem_row_major);
                    wmma::fill_fragment(accA[m], 0.0f);
                    wmma::fill_fragment(accB[m], 0.0f);
                }
            }
            __syncthreads();   // gh reads done before stage-B overwrites buffer

            if (layer > 0) {
                // ---- stage B: input ys[layer-1][t] rows ----
                const unsigned int* src = g_ys + (((size_t)(layer - 1) * T_ + t) * B_ + rowbase) * H_;
                for (int i = tid; i < 4096; i += NTHR) {
                    int row = i >> 7;
                    int cc  = (i & 127) * 4;
                    uint4 v = __ldcg((const uint4*)(src + (size_t)row * H_ + cc));
                    unsigned int h01 = __byte_perm(v.x, v.y, 0x5410);
                    unsigned int l01 = __byte_perm(v.x, v.y, 0x7632);
                    unsigned int h23 = __byte_perm(v.z, v.w, 0x5410);
                    unsigned int l23 = __byte_perm(v.z, v.w, 0x7632);
                    *(uint2*)&hh[row * SW + cc] = make_uint2(h01, h23);
                    *(uint2*)&hl[row * SW + cc] = make_uint2(l01, l23);
                }
                __syncthreads();

                // ---- gi MMA: m-interleaved, accumulate into same 4 chains ----
                #pragma unroll
                for (int i = 0; i < 8; i++) {
                    afrag_t ah0, al0, ah1, al1;
                    bfrag_t bwh, bwl;
                    wmma::load_matrix_sync(bwh, wihh + ntile * 16 * SW + kb + i * 16, SW);
                    wmma::load_matrix_sync(bwl, wihl + ntile * 16 * SW + kb + i * 16, SW);
                    wmma::load_matrix_sync(ah0, hh + kb + i * 16, SW);
                    wmma::load_matrix_sync(ah1, hh + 16 * SW + kb + i * 16, SW);
                    wmma::load_matrix_sync(al0, hl + kb + i * 16, SW);
                    wmma::load_matrix_sync(al1, hl + 16 * SW + kb + i * 16, SW);
                    wmma::mma_sync(accA[0], ah0, bwh, accA[0]);
                    wmma::mma_sync(accA[1], ah1, bwh, accA[1]);
                    wmma::mma_sync(accB[0], al0, bwh, accB[0]);
                    wmma::mma_sync(accB[1], al1, bwh, accB[1]);
                    wmma::mma_sync(accA[0], ah0, bwl, accA[0]);
                    wmma::mma_sync(accA[1], ah1, bwl, accA[1]);
                }
            }

            // ---- store partials: r,z fused at cols 0/16; i_n at col 48 ----
            {
                int colb = (ntile < 2) ? ntile * 16 : 48;
                if (ntile < 2 || layer > 0) {
                    #pragma unroll
                    for (int m = 0; m < 2; m++) {
                        #pragma unroll
                        for (int e = 0; e < accA[m].num_elements; e++)
                            accA[m].x[e] += accB[m].x[e];
                        wmma::store_matrix_sync(P + kq * 2048 + m * 16 * 64 + colb, accA[m], 64, wmma::mem_row_major);
                    }
                }
            }
            __syncthreads();

            // ---- epilogue: 512 elements (32 rows x 16 cols) ----
            for (int idx = tid; idx < 512; idx += NTHR) {
                int rr = idx >> 4, j = idx & 15;
                int b = rowbase + rr;
                float pr = 0.f, pz = 0.f, pn = 0.f, pi = 0.f;
                #pragma unroll
                for (int q = 0; q < 4; q++) {
                    int base = q * 2048 + rr * 64;
                    pr += P[base + j];
                    pz += P[base + 16 + j];
                    pn += P[base + 32 + j];
                    pi += P[base + 48 + j];
                }
                float r, z, n;
                if (layer == 0) {
                    const float* gp = gi0 + ((size_t)b * T_ + t) * G3H + (c0 + j);
                    float ir = __ldg(gp), iz = __ldg(gp + H_), in = __ldg(gp + 2 * H_);
                    r = fast_sigmoid(ir + pr + sbh[j]);
                    z = fast_sigmoid(iz + pz + sbh[16 + j]);
                    n = fast_tanh(in + r * (pn + sbh[32 + j]));
                } else {
                    r = fast_sigmoid(pr + sbh[j] + sbi[j]);
                    z = fast_sigmoid(pz + sbh[16 + j] + sbi[16 + j]);
                    n = fast_tanh(pi + sbi[32 + j] + r * (pn + sbh[32 + j]));
                }
                float ho = hof[rr * 16 + j];
                float hn = (1.0f - z) * n + z * ho;
                __nv_bfloat16 hi, lo; split_bf16(hn, hi, lo);
                unsigned int packed = ((unsigned int)__bfloat16_as_ushort(hi)) |
                                      ((unsigned int)__bfloat16_as_ushort(lo) << 16);
                __stcg(&g_ys[(((size_t)layer * T_ + t) * B_ + b) * H_ + c0 + j], packed);
                if (layer == 3)
                    ysout[((size_t)b * T_ + t) * H_ + c0 + j] = hn;
            }
            __syncthreads();
        }   // halves

        // ---- arrive: release this tick's ys writes ----
        if (tid == 0)
            asm volatile("red.release.gpu.global.add.s32 [%0], 1;" :: "l"(mycnt) : "memory");
    }
}

// =================================================================================
// Orchestration — kernel sequence: gemm1(1), gemm0(2), hbinit(3), scan(4 <- ncu)
// =================================================================================
extern "C" void kernel_launch(void* const* d_in, const int* in_sizes, int n_in,
                              void* d_out, int out_size)
{
    const float* x    = (const float*)d_in[0];
    const float* w_in = (const float*)d_in[1];
    const float* b_in = (const float*)d_in[2];
    const float* w_ih = (const float*)d_in[3];
    const float* w_hh = (const float*)d_in[4];
    const float* b_ih = (const float*)d_in[5];
    const float* b_hh = (const float*)d_in[6];
    const float* w_o1 = (const float*)d_in[7];
    const float* b_o1 = (const float*)d_in[8];
    const float* w_o2 = (const float*)d_in[9];
    const float* b_o2 = (const float*)d_in[10];
    float* out = (float*)d_out;
    (void)in_sizes; (void)n_in; (void)out_size;

    float *hA, *hB, *gi;
    cudaGetSymbolAddress((void**)&hA, g_hA);
    cudaGetSymbolAddress((void**)&hB, g_hB);
    cudaGetSymbolAddress((void**)&gi, g_gi);

    cudaFuncSetAttribute(scan_wave, cudaFuncAttributeMaxDynamicSharedMemorySize, SCAN_SMEM);

    dim3 blk(256);

    // 1: input Linear + ReLU -> hA
    gemm_kernel<1><<<dim3(H_ / BN, M_ / BM), blk>>>(x, w_in, b_in, hA, M_, H_, H_);
    // 2: layer-0 gi (bias b_ih[0] folded)
    gemm_kernel<0><<<dim3(G3H / BN, M_ / BM), blk>>>(
        hA, w_ih, b_ih, gi, M_, G3H, H_);
    // 3: zero wavefront counters
    hbinit_kernel<<<1, 256>>>();
    // 4: the whole 4-layer wavefront recurrence (ncu captured slot)
    scan_wave<<<NBLK * L_, NTHR, SCAN_SMEM>>>(gi, w_ih, w_hh, b_ih, b_hh, hA);
    // 5/6: output MLP
    gemm_kernel<1><<<dim3(H_ / BN, M_ / BM), blk>>>(hA, w_o1, b_o1, hB, M_, H_, H_);
    gemm_kernel<0><<<dim3(H_ / BN, M_ / BM), blk>>>(hB, w_o2, b_o2, out, M_, H_, H_);
}